// round 15
// baseline (speedup 1.0000x reference)
#include <cuda_runtime.h>
#include <cuda_bf16.h>
#include <math.h>
#include <stdint.h>

#define TOKENS  8192
#define D_MODEL 2048
#define D_FF    8192

// ---------------- scratch (static device globals) ----------------
__device__ double        g_part[2][1024];
__device__ float         g_wscale[2];
__device__ __nv_bfloat16 g_w1q[(size_t)D_FF * D_MODEL];
__device__ __nv_bfloat16 g_w2q[(size_t)D_MODEL * D_FF];
__device__ __nv_bfloat16 g_xq [(size_t)TOKENS * D_MODEL];
__device__ float         g_xinv[TOKENS];
__device__ float         g_h  [(size_t)TOKENS * D_FF];   // pre-GELU linear output
__device__ __nv_bfloat16 g_hq [(size_t)TOKENS * D_FF];
__device__ float         g_hinv[TOKENS];

// ---------------- PTX helpers ----------------
__device__ __forceinline__ uint32_t s2u(const void* p) {
    uint32_t a;
    asm("{ .reg .u64 t; cvta.to.shared.u64 t, %1; cvt.u32.u64 %0, t; }" : "=r"(a) : "l"(p));
    return a;
}
#define CP_ASYNC16(s, g) \
    asm volatile("cp.async.cg.shared.global [%0], [%1], 16;" :: "r"(s), "l"(g) : "memory")
#define CP_COMMIT()  asm volatile("cp.async.commit_group;" ::: "memory")
#define CP_WAIT(n)   asm volatile("cp.async.wait_group %0;" :: "n"(n) : "memory")

#define LDSM_X4(r, a) \
    asm volatile("ldmatrix.sync.aligned.m8n8.x4.shared.b16 {%0,%1,%2,%3}, [%4];" \
        : "=r"((r)[0]), "=r"((r)[1]), "=r"((r)[2]), "=r"((r)[3]) : "r"(a))

#define MMA_BF16(d, a, b0v, b1v) \
    asm volatile("mma.sync.aligned.m16n8k16.row.col.f32.bf16.bf16.f32 " \
        "{%0,%1,%2,%3}, {%4,%5,%6,%7}, {%8,%9}, {%0,%1,%2,%3};" \
        : "+f"((d)[0]), "+f"((d)[1]), "+f"((d)[2]), "+f"((d)[3]) \
        : "r"((a)[0]), "r"((a)[1]), "r"((a)[2]), "r"((a)[3]), "r"(b0v), "r"(b1v))

// ---------------- stage ROWS x 64 bf16 (128B/row), XOR-swizzled, 128 threads ----------------
template <int ROWS>
__device__ __forceinline__ void stage_tile(const __nv_bfloat16* g, int ld,
                                           uint32_t sbase, int tid) {
#pragma unroll
    for (int it = 0; it < ROWS / 16; ++it) {
        int idx = tid + it * 128;
        int row = idx >> 3, c = idx & 7;
        uint32_t saddr = sbase + row * 128 + ((c ^ (row & 7)) << 4);
        CP_ASYNC16(saddr, (const char*)(g + (size_t)row * ld) + c * 16);
    }
}

// ---------------- bf16 HMMA GEMM: out[M,N] = A[M,K] * B[N,K]^T (exact int) ----------------
// block 128x128, 4 warps (2x2), warp tile 64x64, 3-stage cp.async pipeline,
// staging interleaved with the 4 ks sub-steps. MODE 1 stores RAW linear output
// (GELU deferred to ln_quant_h); MODE 2 stores final out. moff = M-block offset.
#define STAGE_BYTES 32768
template <int MODE>
__global__ void __launch_bounds__(128, 2) gemm_hmma(const float* __restrict__ bias,
                                                    float* __restrict__ outp, int moff) {
    extern __shared__ __align__(128) char smem[];

    constexpr int K      = (MODE == 1) ? D_MODEL : D_FF;
    constexpr int KITERS = K / 64;
    constexpr int LDOUT  = (MODE == 1) ? D_FF : D_MODEL;

    const __nv_bfloat16* A = (MODE == 1) ? g_xq : g_hq;
    const __nv_bfloat16* B = (MODE == 1) ? g_w1q : g_w2q;
    const float* rowinv = (MODE == 1) ? g_xinv : g_hinv;
    float* out = (MODE == 1) ? g_h : outp;

    const int tid = threadIdx.x;
    const int wid = tid >> 5, lane = tid & 31;
    const int warpM = wid >> 1, warpN = wid & 1;
    const int m0 = (blockIdx.y + moff) * 128, n0 = blockIdx.x * 128;

    const __nv_bfloat16* Abase = A + (size_t)m0 * K;
    const __nv_bfloat16* Bbase = B + (size_t)n0 * K;

    uint32_t sbase = s2u(smem);
    const int lr = lane & 7, gq = lane >> 3;

    const uint32_t aRow = (uint32_t)(warpM * 64 + lr + ((gq & 1) << 3));
    const uint32_t bRow = (uint32_t)(warpN * 64 + lr + ((gq >> 1) << 3));
    const int aCsel = gq >> 1;
    const int bCsel = gq & 1;

    float acc[4][8][4];
#pragma unroll
    for (int i = 0; i < 4; i++)
#pragma unroll
        for (int j = 0; j < 8; j++)
#pragma unroll
            for (int r = 0; r < 4; r++) acc[i][j][r] = 0.f;

    // prologue: stages 0 and 1
    stage_tile<128>(Abase, K, sbase, tid);
    stage_tile<128>(Bbase, K, sbase + 16384, tid);
    CP_COMMIT();
    stage_tile<128>(Abase + 64, K, sbase + STAGE_BYTES, tid);
    stage_tile<128>(Bbase + 64, K, sbase + STAGE_BYTES + 16384, tid);
    CP_COMMIT();

    for (int kt = 0; kt < KITERS; ++kt) {
        CP_WAIT(1);
        __syncthreads();   // stage-kt visible to all; prior-iter reads complete

        const bool doStage = (kt + 2 < KITERS);
        const uint32_t sn = sbase + ((kt + 2) % 3) * STAGE_BYTES;
        const __nv_bfloat16* An = Abase + (kt + 2) * 64;
        const __nv_bfloat16* Bn = Bbase + (kt + 2) * 64;

        const uint32_t sA = sbase + (kt % 3) * STAGE_BYTES;
        const uint32_t aLane = sA + aRow * 128;
        const uint32_t bLane = sA + 16384 + bRow * 128;
#pragma unroll
        for (int ks = 0; ks < 4; ++ks) {
            // interleave a quarter of next-next-stage staging with this ks block
            if (doStage) {
#pragma unroll
                for (int it = 2 * ks; it < 2 * ks + 2; ++it) {
                    int idx = tid + it * 128;
                    int row = idx >> 3, c = idx & 7;
                    uint32_t off = (uint32_t)(row * 128 + ((c ^ (row & 7)) << 4));
                    CP_ASYNC16(sn + off, (const char*)(An + (size_t)row * K) + c * 16);
                    CP_ASYNC16(sn + 16384 + off, (const char*)(Bn + (size_t)row * K) + c * 16);
                }
            }
            uint32_t ar[4][4], br[4][4];
            const uint32_t ca = (uint32_t)(((ks * 2 + aCsel) ^ lr) << 4);
            const uint32_t cb = (uint32_t)(((ks * 2 + bCsel) ^ lr) << 4);
#pragma unroll
            for (int i = 0; i < 4; i++) LDSM_X4(ar[i], aLane + i * 2048 + ca);
#pragma unroll
            for (int jp = 0; jp < 4; jp++) LDSM_X4(br[jp], bLane + jp * 2048 + cb);
#pragma unroll
            for (int i = 0; i < 4; i++)
#pragma unroll
                for (int j = 0; j < 8; j++)
                    MMA_BF16(acc[i][j], ar[i], br[j >> 1][(j & 1) * 2],
                             br[j >> 1][(j & 1) * 2 + 1]);
        }
        CP_COMMIT();       // exactly one group per iter
    }

    // ---------------- epilogue: scale + bias, float2 stores (no GELU here) ----------------
    const float ws = g_wscale[MODE - 1];
    const int rbase = m0 + warpM * 64 + (lane >> 2);
    const int cbase = n0 + warpN * 64 + (lane & 3) * 2;
#pragma unroll
    for (int i = 0; i < 4; i++) {
        const int r0 = rbase + i * 16;
        const float sc0 = rowinv[r0] * ws;
        const float sc1 = rowinv[r0 + 8] * ws;
#pragma unroll
        for (int j = 0; j < 8; j++) {
            const int c = cbase + j * 8;
            const float bx = bias[c], by = bias[c + 1];
            float2 v0, v1;
            v0.x = acc[i][j][0] * sc0 + bx;
            v0.y = acc[i][j][1] * sc0 + by;
            v1.x = acc[i][j][2] * sc1 + bx;
            v1.y = acc[i][j][3] * sc1 + by;
            *(float2*)(out + (size_t)r0 * LDOUT + c) = v0;
            *(float2*)(out + (size_t)(r0 + 8) * LDOUT + c) = v1;
        }
    }
}

// ---------------- weight absmean partials, both weights in one launch ----------------
__global__ void absmean_stage1(const float* __restrict__ w1, const float* __restrict__ w2,
                               size_t n) {
    __shared__ double sh[256];
    const int idx = blockIdx.y;
    const float* w = idx ? w2 : w1;
    double s = 0.0;
    for (size_t i = (size_t)blockIdx.x * 256 + threadIdx.x; i < n; i += (size_t)256 * 1024)
        s += fabsf(w[i]);
    sh[threadIdx.x] = s; __syncthreads();
    for (int st = 128; st > 0; st >>= 1) {
        if (threadIdx.x < st) sh[threadIdx.x] += sh[threadIdx.x + st];
        __syncthreads();
    }
    if (threadIdx.x == 0) g_part[idx][blockIdx.x] = sh[0];
}

// ---------------- ternary weight quant -> bf16, both weights, fused scale fold ----------------
__global__ void quant_w_kernel(const float* __restrict__ w1, const float* __restrict__ w2,
                               size_t n) {
    __shared__ double sh[256];
    const int idx = blockIdx.y;
    const int tid = threadIdx.x;
    double s = g_part[idx][tid] + g_part[idx][tid + 256] +
               g_part[idx][tid + 512] + g_part[idx][tid + 768];
    sh[tid] = s; __syncthreads();
    for (int st = 128; st > 0; st >>= 1) {
        if (tid < st) sh[tid] += sh[tid + st];
        __syncthreads();
    }
    const float sc = (float)fmax(sh[0] / (double)n, 1e-8);
    if (blockIdx.x == 0 && tid == 0) g_wscale[idx] = sc;

    const float* w = idx ? w2 : w1;
    __nv_bfloat16* q = idx ? g_w2q : g_w1q;
    for (size_t i = (size_t)blockIdx.x * blockDim.x + tid; i < n;
         i += (size_t)4096 * blockDim.x) {
        float v = rintf(w[i] / sc);
        v = fmaxf(-1.0f, fminf(1.0f, v));
        q[i] = __float2bfloat16(v);
    }
}

#define QV(a, scale) fminf(127.f, fmaxf(-128.f, rintf((a) * (scale))))

// fast erf (Abramowitz-Stegun 7.1.26, |abs err| ~1.5e-7) -> exact-enough GELU
__device__ __forceinline__ float gelu_fast(float x) {
    float z = x * 0.7071067811865476f;
    float az = fabsf(z);
    float t = __fdividef(1.0f, 1.0f + 0.3275911f * az);
    float p = ((((1.061405429f * t - 1.453152027f) * t + 1.421413741f) * t
               - 0.284496736f) * t + 0.254829592f) * t;
    float er = 1.0f - p * __expf(-az * az);
    er = copysignf(er, z);
    return 0.5f * x * (1.0f + er);
}

// ---------------- fused LN + per-token absmax int8 fake-quant -> bf16 (x: d=2048) ----------------
__global__ void ln_quant_x_kernel(const float* __restrict__ x) {
    __shared__ float sh[24];
    const int t = blockIdx.x, tid = threadIdx.x;
    const int wid = tid >> 5, lane = tid & 31;
    const float4* rp = (const float4*)(x + (size_t)t * D_MODEL);
    float4 v0 = rp[tid], v1 = rp[tid + 256];

    float s = v0.x + v0.y + v0.z + v0.w + v1.x + v1.y + v1.z + v1.w;
    for (int o = 16; o; o >>= 1) s += __shfl_xor_sync(0xffffffffu, s, o);
    if (lane == 0) sh[wid] = s;
    __syncthreads();
    float mu = (((sh[0] + sh[1]) + (sh[2] + sh[3])) + ((sh[4] + sh[5]) + (sh[6] + sh[7])))
               * (1.0f / D_MODEL);

    v0.x -= mu; v0.y -= mu; v0.z -= mu; v0.w -= mu;
    v1.x -= mu; v1.y -= mu; v1.z -= mu; v1.w -= mu;
    float vs = v0.x*v0.x + v0.y*v0.y + v0.z*v0.z + v0.w*v0.w
             + v1.x*v1.x + v1.y*v1.y + v1.z*v1.z + v1.w*v1.w;
    for (int o = 16; o; o >>= 1) vs += __shfl_xor_sync(0xffffffffu, vs, o);
    if (lane == 0) sh[8 + wid] = vs;
    __syncthreads();
    float var = (((sh[8] + sh[9]) + (sh[10] + sh[11])) + ((sh[12] + sh[13]) + (sh[14] + sh[15])))
                * (1.0f / D_MODEL);
    float rstd = rsqrtf(var + 1e-5f);

    v0.x *= rstd; v0.y *= rstd; v0.z *= rstd; v0.w *= rstd;
    v1.x *= rstd; v1.y *= rstd; v1.z *= rstd; v1.w *= rstd;
    float am = fmaxf(fmaxf(fmaxf(fabsf(v0.x), fabsf(v0.y)), fmaxf(fabsf(v0.z), fabsf(v0.w))),
                     fmaxf(fmaxf(fabsf(v1.x), fabsf(v1.y)), fmaxf(fabsf(v1.z), fabsf(v1.w))));
    for (int o = 16; o; o >>= 1) am = fmaxf(am, __shfl_xor_sync(0xffffffffu, am, o));
    if (lane == 0) sh[16 + wid] = am;
    __syncthreads();
    float amax = fmaxf(fmaxf(fmaxf(sh[16], sh[17]), fmaxf(sh[18], sh[19])),
                       fmaxf(fmaxf(sh[20], sh[21]), fmaxf(sh[22], sh[23])));
    amax = fmaxf(amax, 1e-5f);
    float scale = 127.0f / amax;

    __nv_bfloat162* qp = (__nv_bfloat162*)(g_xq + (size_t)t * D_MODEL);
    qp[2 * tid + 0]         = __floats2bfloat162_rn(QV(v0.x, scale), QV(v0.y, scale));
    qp[2 * tid + 1]         = __floats2bfloat162_rn(QV(v0.z, scale), QV(v0.w, scale));
    qp[2 * (tid + 256) + 0] = __floats2bfloat162_rn(QV(v1.x, scale), QV(v1.y, scale));
    qp[2 * (tid + 256) + 1] = __floats2bfloat162_rn(QV(v1.z, scale), QV(v1.w, scale));
    if (tid == 0) g_xinv[t] = amax * (1.0f / 127.0f);
}

// ---------------- GELU + LN + quant (h: d=8192) -> bf16, 256 threads ----------------
__global__ void ln_quant_h_kernel(int toff) {
    __shared__ float sh[24];
    const int t = blockIdx.x + toff, tid = threadIdx.x;
    const int wid = tid >> 5, lane = tid & 31;
    const float4* rp = (const float4*)(g_h + (size_t)t * D_FF);
    float4 v[8];
    float s = 0.f;
#pragma unroll
    for (int j = 0; j < 8; j++) v[j] = rp[j * 256 + tid];
#pragma unroll
    for (int j = 0; j < 8; j++) {
        v[j].x = gelu_fast(v[j].x); v[j].y = gelu_fast(v[j].y);
        v[j].z = gelu_fast(v[j].z); v[j].w = gelu_fast(v[j].w);
        s += v[j].x + v[j].y + v[j].z + v[j].w;
    }
    for (int o = 16; o; o >>= 1) s += __shfl_xor_sync(0xffffffffu, s, o);
    if (lane == 0) sh[wid] = s;
    __syncthreads();
    float mu = (((sh[0] + sh[1]) + (sh[2] + sh[3])) + ((sh[4] + sh[5]) + (sh[6] + sh[7])))
               * (1.0f / D_FF);

    float vs = 0.f;
#pragma unroll
    for (int j = 0; j < 8; j++) {
        v[j].x -= mu; v[j].y -= mu; v[j].z -= mu; v[j].w -= mu;
        vs += v[j].x*v[j].x + v[j].y*v[j].y + v[j].z*v[j].z + v[j].w*v[j].w;
    }
    for (int o = 16; o; o >>= 1) vs += __shfl_xor_sync(0xffffffffu, vs, o);
    if (lane == 0) sh[8 + wid] = vs;
    __syncthreads();
    float var = (((sh[8] + sh[9]) + (sh[10] + sh[11])) + ((sh[12] + sh[13]) + (sh[14] + sh[15])))
                * (1.0f / D_FF);
    float rstd = rsqrtf(var + 1e-5f);

    float am = 0.f;
#pragma unroll
    for (int j = 0; j < 8; j++) {
        v[j].x *= rstd; v[j].y *= rstd; v[j].z *= rstd; v[j].w *= rstd;
        am = fmaxf(am, fmaxf(fmaxf(fabsf(v[j].x), fabsf(v[j].y)), fmaxf(fabsf(v[j].z), fabsf(v[j].w))));
    }
    for (int o = 16; o; o >>= 1) am = fmaxf(am, __shfl_xor_sync(0xffffffffu, am, o));
    if (lane == 0) sh[16 + wid] = am;
    __syncthreads();
    float amax = fmaxf(fmaxf(fmaxf(sh[16], sh[17]), fmaxf(sh[18], sh[19])),
                       fmaxf(fmaxf(sh[20], sh[21]), fmaxf(sh[22], sh[23])));
    amax = fmaxf(amax, 1e-5f);
    float scale = 127.0f / amax;

    __nv_bfloat162* qp = (__nv_bfloat162*)(g_hq + (size_t)t * D_FF);
#pragma unroll
    for (int j = 0; j < 8; j++) {
        qp[2 * (j * 256 + tid) + 0] = __floats2bfloat162_rn(QV(v[j].x, scale), QV(v[j].y, scale));
        qp[2 * (j * 256 + tid) + 1] = __floats2bfloat162_rn(QV(v[j].z, scale), QV(v[j].w, scale));
    }
    if (tid == 0) g_hinv[t] = amax * (1.0f / 127.0f);
}

// ---------------- launch: forked-stream overlapped schedule ----------------
extern "C" void kernel_launch(void* const* d_in, const int* in_sizes, int n_in,
                              void* d_out, int out_size) {
    (void)in_sizes; (void)n_in; (void)out_size;
    const float* x  = (const float*)d_in[0];
    const float* w1 = (const float*)d_in[1];
    const float* b1 = (const float*)d_in[2];
    const float* w2 = (const float*)d_in[3];
    const float* b2 = (const float*)d_in[4];
    float* out = (float*)d_out;

    const size_t NW = (size_t)D_FF * D_MODEL;
    const int GEMM_SMEM = 3 * STAGE_BYTES;  // 96 KB

    cudaFuncSetAttribute(gemm_hmma<1>, cudaFuncAttributeMaxDynamicSharedMemorySize, GEMM_SMEM);
    cudaFuncSetAttribute(gemm_hmma<2>, cudaFuncAttributeMaxDynamicSharedMemorySize, GEMM_SMEM);

    // one-time side stream + events (created on the first, non-captured, correctness call)
    static cudaStream_t sSide = [] {
        cudaStream_t s; cudaStreamCreateWithFlags(&s, cudaStreamNonBlocking); return s;
    }();
    static cudaEvent_t eFork = [] {
        cudaEvent_t e; cudaEventCreateWithFlags(&e, cudaEventDisableTiming); return e;
    }();
    static cudaEvent_t eX = [] {
        cudaEvent_t e; cudaEventCreateWithFlags(&e, cudaEventDisableTiming); return e;
    }();
    static cudaEvent_t eG1a = [] {
        cudaEvent_t e; cudaEventCreateWithFlags(&e, cudaEventDisableTiming); return e;
    }();
    static cudaEvent_t eSide = [] {
        cudaEvent_t e; cudaEventCreateWithFlags(&e, cudaEventDisableTiming); return e;
    }();

    // resolve the "main" stream: whichever default stream the harness is capturing
    cudaStream_t M = cudaStreamLegacy;
    cudaStreamCaptureStatus cst = cudaStreamCaptureStatusNone;
    cudaStreamIsCapturing(cudaStreamPerThread, &cst);
    if (cst != cudaStreamCaptureStatusNone) M = cudaStreamPerThread;

    // fork: side stream joins the capture/ordering context
    cudaEventRecord(eFork, M);
    cudaStreamWaitEvent(sSide, eFork, 0);

    // side: ln_quant_x (independent of weight chain)
    ln_quant_x_kernel<<<TOKENS, 256, 0, sSide>>>(x);
    cudaEventRecord(eX, sSide);

    // main: weight chain
    absmean_stage1<<<dim3(1024, 2), 256, 0, M>>>(w1, w2, NW);
    quant_w_kernel<<<dim3(4096, 2), 256, 0, M>>>(w1, w2, NW);

    // main: gemm1 first half (needs xq + w1q)
    cudaStreamWaitEvent(M, eX, 0);
    gemm_hmma<1><<<dim3(D_FF / 128, 32), 128, GEMM_SMEM, M>>>(b1, nullptr, 0);
    cudaEventRecord(eG1a, M);

    // main: gemm1 second half   |   side: ln_h + gemm2 for first half rows
    gemm_hmma<1><<<dim3(D_FF / 128, 32), 128, GEMM_SMEM, M>>>(b1, nullptr, 32);

    cudaStreamWaitEvent(sSide, eG1a, 0);
    ln_quant_h_kernel<<<TOKENS / 2, 256, 0, sSide>>>(0);
    gemm_hmma<2><<<dim3(D_MODEL / 128, 32), 128, GEMM_SMEM, sSide>>>(b2, out, 0);
    cudaEventRecord(eSide, sSide);

    // main: second half rows
    ln_quant_h_kernel<<<TOKENS / 2, 256, 0, M>>>(TOKENS / 2);
    gemm_hmma<2><<<dim3(D_MODEL / 128, 32), 128, GEMM_SMEM, M>>>(b2, out, 32);

    // join side branch back into main before capture ends
    cudaStreamWaitEvent(M, eSide, 0);
}

// round 16
// speedup vs baseline: 1.0047x; 1.0047x over previous
#include <cuda_runtime.h>
#include <cuda_bf16.h>
#include <math.h>
#include <stdint.h>

#define TOKENS  8192
#define D_MODEL 2048
#define D_FF    8192

// ---------------- scratch (static device globals) ----------------
__device__ double        g_part[2][1024];
__device__ float         g_wscale[2];
__device__ __nv_bfloat16 g_w1q[(size_t)D_FF * D_MODEL];
__device__ __nv_bfloat16 g_w2q[(size_t)D_MODEL * D_FF];
__device__ __nv_bfloat16 g_xq [(size_t)TOKENS * D_MODEL];
__device__ float         g_xinv[TOKENS];
__device__ float         g_h  [(size_t)TOKENS * D_FF];   // pre-GELU linear output
__device__ __nv_bfloat16 g_hq [(size_t)TOKENS * D_FF];
__device__ float         g_hinv[TOKENS];

// ---------------- PTX helpers ----------------
__device__ __forceinline__ uint32_t s2u(const void* p) {
    uint32_t a;
    asm("{ .reg .u64 t; cvta.to.shared.u64 t, %1; cvt.u32.u64 %0, t; }" : "=r"(a) : "l"(p));
    return a;
}
#define CP_ASYNC16(s, g) \
    asm volatile("cp.async.cg.shared.global [%0], [%1], 16;" :: "r"(s), "l"(g) : "memory")
#define CP_COMMIT()  asm volatile("cp.async.commit_group;" ::: "memory")
#define CP_WAIT(n)   asm volatile("cp.async.wait_group %0;" :: "n"(n) : "memory")

#define LDSM_X4(r, a) \
    asm volatile("ldmatrix.sync.aligned.m8n8.x4.shared.b16 {%0,%1,%2,%3}, [%4];" \
        : "=r"((r)[0]), "=r"((r)[1]), "=r"((r)[2]), "=r"((r)[3]) : "r"(a))

#define MMA_BF16(d, a, b0v, b1v) \
    asm volatile("mma.sync.aligned.m16n8k16.row.col.f32.bf16.bf16.f32 " \
        "{%0,%1,%2,%3}, {%4,%5,%6,%7}, {%8,%9}, {%0,%1,%2,%3};" \
        : "+f"((d)[0]), "+f"((d)[1]), "+f"((d)[2]), "+f"((d)[3]) \
        : "r"((a)[0]), "r"((a)[1]), "r"((a)[2]), "r"((a)[3]), "r"(b0v), "r"(b1v))

// ---------------- stage ROWS x 64 bf16 (128B/row), XOR-swizzled, 128 threads ----------------
template <int ROWS>
__device__ __forceinline__ void stage_tile(const __nv_bfloat16* g, int ld,
                                           uint32_t sbase, int tid) {
#pragma unroll
    for (int it = 0; it < ROWS / 16; ++it) {
        int idx = tid + it * 128;
        int row = idx >> 3, c = idx & 7;
        uint32_t saddr = sbase + row * 128 + ((c ^ (row & 7)) << 4);
        CP_ASYNC16(saddr, (const char*)(g + (size_t)row * ld) + c * 16);
    }
}

// ---------------- bf16 HMMA GEMM: out[M,N] = A[M,K] * B[N,K]^T (exact int) ----------------
// block 128x128, 4 warps (2x2), warp tile 64x64, 3-stage cp.async pipeline,
// staging interleaved with the 4 ks sub-steps. MODE 1 stores RAW linear output
// (GELU deferred to ln_quant_h); MODE 2 stores final out.
#define STAGE_BYTES 32768
template <int MODE>
__global__ void __launch_bounds__(128, 2) gemm_hmma(const float* __restrict__ bias,
                                                    float* __restrict__ outp) {
    extern __shared__ __align__(128) char smem[];

    constexpr int K      = (MODE == 1) ? D_MODEL : D_FF;
    constexpr int KITERS = K / 64;
    constexpr int LDOUT  = (MODE == 1) ? D_FF : D_MODEL;

    const __nv_bfloat16* A = (MODE == 1) ? g_xq : g_hq;
    const __nv_bfloat16* B = (MODE == 1) ? g_w1q : g_w2q;
    const float* rowinv = (MODE == 1) ? g_xinv : g_hinv;
    float* out = (MODE == 1) ? g_h : outp;

    const int tid = threadIdx.x;
    const int wid = tid >> 5, lane = tid & 31;
    const int warpM = wid >> 1, warpN = wid & 1;
    const int m0 = blockIdx.y * 128, n0 = blockIdx.x * 128;

    const __nv_bfloat16* Abase = A + (size_t)m0 * K;
    const __nv_bfloat16* Bbase = B + (size_t)n0 * K;

    uint32_t sbase = s2u(smem);
    const int lr = lane & 7, gq = lane >> 3;

    const uint32_t aRow = (uint32_t)(warpM * 64 + lr + ((gq & 1) << 3));
    const uint32_t bRow = (uint32_t)(warpN * 64 + lr + ((gq >> 1) << 3));
    const int aCsel = gq >> 1;
    const int bCsel = gq & 1;

    float acc[4][8][4];
#pragma unroll
    for (int i = 0; i < 4; i++)
#pragma unroll
        for (int j = 0; j < 8; j++)
#pragma unroll
            for (int r = 0; r < 4; r++) acc[i][j][r] = 0.f;

    // prologue: stages 0 and 1
    stage_tile<128>(Abase, K, sbase, tid);
    stage_tile<128>(Bbase, K, sbase + 16384, tid);
    CP_COMMIT();
    stage_tile<128>(Abase + 64, K, sbase + STAGE_BYTES, tid);
    stage_tile<128>(Bbase + 64, K, sbase + STAGE_BYTES + 16384, tid);
    CP_COMMIT();

    for (int kt = 0; kt < KITERS; ++kt) {
        CP_WAIT(1);
        __syncthreads();   // stage-kt visible to all; prior-iter reads complete

        const bool doStage = (kt + 2 < KITERS);
        const uint32_t sn = sbase + ((kt + 2) % 3) * STAGE_BYTES;
        const __nv_bfloat16* An = Abase + (kt + 2) * 64;
        const __nv_bfloat16* Bn = Bbase + (kt + 2) * 64;

        const uint32_t sA = sbase + (kt % 3) * STAGE_BYTES;
        const uint32_t aLane = sA + aRow * 128;
        const uint32_t bLane = sA + 16384 + bRow * 128;
#pragma unroll
        for (int ks = 0; ks < 4; ++ks) {
            // interleave a quarter of next-next-stage staging with this ks block
            if (doStage) {
#pragma unroll
                for (int it = 2 * ks; it < 2 * ks + 2; ++it) {
                    int idx = tid + it * 128;
                    int row = idx >> 3, c = idx & 7;
                    uint32_t off = (uint32_t)(row * 128 + ((c ^ (row & 7)) << 4));
                    CP_ASYNC16(sn + off, (const char*)(An + (size_t)row * K) + c * 16);
                    CP_ASYNC16(sn + 16384 + off, (const char*)(Bn + (size_t)row * K) + c * 16);
                }
            }
            uint32_t ar[4][4], br[4][4];
            const uint32_t ca = (uint32_t)(((ks * 2 + aCsel) ^ lr) << 4);
            const uint32_t cb = (uint32_t)(((ks * 2 + bCsel) ^ lr) << 4);
#pragma unroll
            for (int i = 0; i < 4; i++) LDSM_X4(ar[i], aLane + i * 2048 + ca);
#pragma unroll
            for (int jp = 0; jp < 4; jp++) LDSM_X4(br[jp], bLane + jp * 2048 + cb);
#pragma unroll
            for (int i = 0; i < 4; i++)
#pragma unroll
                for (int j = 0; j < 8; j++)
                    MMA_BF16(acc[i][j], ar[i], br[j >> 1][(j & 1) * 2],
                             br[j >> 1][(j & 1) * 2 + 1]);
        }
        CP_COMMIT();       // exactly one group per iter
    }

    // ---------------- epilogue: scale + bias, float2 stores (no GELU here) ----------------
    const float ws = g_wscale[MODE - 1];
    const int rbase = m0 + warpM * 64 + (lane >> 2);
    const int cbase = n0 + warpN * 64 + (lane & 3) * 2;
#pragma unroll
    for (int i = 0; i < 4; i++) {
        const int r0 = rbase + i * 16;
        const float sc0 = rowinv[r0] * ws;
        const float sc1 = rowinv[r0 + 8] * ws;
#pragma unroll
        for (int j = 0; j < 8; j++) {
            const int c = cbase + j * 8;
            const float bx = bias[c], by = bias[c + 1];
            float2 v0, v1;
            v0.x = acc[i][j][0] * sc0 + bx;
            v0.y = acc[i][j][1] * sc0 + by;
            v1.x = acc[i][j][2] * sc1 + bx;
            v1.y = acc[i][j][3] * sc1 + by;
            *(float2*)(out + (size_t)r0 * LDOUT + c) = v0;
            *(float2*)(out + (size_t)(r0 + 8) * LDOUT + c) = v1;
        }
    }
}

// ---------------- weight absmean partials, both weights in one launch ----------------
__global__ void absmean_stage1(const float* __restrict__ w1, const float* __restrict__ w2,
                               size_t n) {
    __shared__ double sh[256];
    const int idx = blockIdx.y;
    const float* w = idx ? w2 : w1;
    double s = 0.0;
    for (size_t i = (size_t)blockIdx.x * 256 + threadIdx.x; i < n; i += (size_t)256 * 1024)
        s += fabsf(w[i]);
    sh[threadIdx.x] = s; __syncthreads();
    for (int st = 128; st > 0; st >>= 1) {
        if (threadIdx.x < st) sh[threadIdx.x] += sh[threadIdx.x + st];
        __syncthreads();
    }
    if (threadIdx.x == 0) g_part[idx][blockIdx.x] = sh[0];
}

// ---------------- ternary weight quant -> bf16, both weights, fused scale fold ----------------
__global__ void quant_w_kernel(const float* __restrict__ w1, const float* __restrict__ w2,
                               size_t n) {
    __shared__ double sh[256];
    const int idx = blockIdx.y;
    const int tid = threadIdx.x;
    double s = g_part[idx][tid] + g_part[idx][tid + 256] +
               g_part[idx][tid + 512] + g_part[idx][tid + 768];
    sh[tid] = s; __syncthreads();
    for (int st = 128; st > 0; st >>= 1) {
        if (tid < st) sh[tid] += sh[tid + st];
        __syncthreads();
    }
    const float sc = (float)fmax(sh[0] / (double)n, 1e-8);
    if (blockIdx.x == 0 && tid == 0) g_wscale[idx] = sc;

    const float* w = idx ? w2 : w1;
    __nv_bfloat16* q = idx ? g_w2q : g_w1q;
    for (size_t i = (size_t)blockIdx.x * blockDim.x + tid; i < n;
         i += (size_t)4096 * blockDim.x) {
        float v = rintf(w[i] / sc);
        v = fmaxf(-1.0f, fminf(1.0f, v));
        q[i] = __float2bfloat16(v);
    }
}

#define QV(a, scale) fminf(127.f, fmaxf(-128.f, rintf((a) * (scale))))

// fast erf (Abramowitz-Stegun 7.1.26, |abs err| ~1.5e-7) -> exact-enough GELU
__device__ __forceinline__ float gelu_fast(float x) {
    float z = x * 0.7071067811865476f;
    float az = fabsf(z);
    float t = __fdividef(1.0f, 1.0f + 0.3275911f * az);
    float p = ((((1.061405429f * t - 1.453152027f) * t + 1.421413741f) * t
               - 0.284496736f) * t + 0.254829592f) * t;
    float er = 1.0f - p * __expf(-az * az);
    er = copysignf(er, z);
    return 0.5f * x * (1.0f + er);
}

// ---------------- fused LN + per-token absmax int8 fake-quant -> bf16 (x: d=2048) ----------------
__global__ void ln_quant_x_kernel(const float* __restrict__ x) {
    __shared__ float sh[24];
    const int t = blockIdx.x, tid = threadIdx.x;
    const int wid = tid >> 5, lane = tid & 31;
    const float4* rp = (const float4*)(x + (size_t)t * D_MODEL);
    float4 v0 = rp[tid], v1 = rp[tid + 256];

    float s = v0.x + v0.y + v0.z + v0.w + v1.x + v1.y + v1.z + v1.w;
    for (int o = 16; o; o >>= 1) s += __shfl_xor_sync(0xffffffffu, s, o);
    if (lane == 0) sh[wid] = s;
    __syncthreads();
    float mu = (((sh[0] + sh[1]) + (sh[2] + sh[3])) + ((sh[4] + sh[5]) + (sh[6] + sh[7])))
               * (1.0f / D_MODEL);

    v0.x -= mu; v0.y -= mu; v0.z -= mu; v0.w -= mu;
    v1.x -= mu; v1.y -= mu; v1.z -= mu; v1.w -= mu;
    float vs = v0.x*v0.x + v0.y*v0.y + v0.z*v0.z + v0.w*v0.w
             + v1.x*v1.x + v1.y*v1.y + v1.z*v1.z + v1.w*v1.w;
    for (int o = 16; o; o >>= 1) vs += __shfl_xor_sync(0xffffffffu, vs, o);
    if (lane == 0) sh[8 + wid] = vs;
    __syncthreads();
    float var = (((sh[8] + sh[9]) + (sh[10] + sh[11])) + ((sh[12] + sh[13]) + (sh[14] + sh[15])))
                * (1.0f / D_MODEL);
    float rstd = rsqrtf(var + 1e-5f);

    v0.x *= rstd; v0.y *= rstd; v0.z *= rstd; v0.w *= rstd;
    v1.x *= rstd; v1.y *= rstd; v1.z *= rstd; v1.w *= rstd;
    float am = fmaxf(fmaxf(fmaxf(fabsf(v0.x), fabsf(v0.y)), fmaxf(fabsf(v0.z), fabsf(v0.w))),
                     fmaxf(fmaxf(fabsf(v1.x), fabsf(v1.y)), fmaxf(fabsf(v1.z), fabsf(v1.w))));
    for (int o = 16; o; o >>= 1) am = fmaxf(am, __shfl_xor_sync(0xffffffffu, am, o));
    if (lane == 0) sh[16 + wid] = am;
    __syncthreads();
    float amax = fmaxf(fmaxf(fmaxf(sh[16], sh[17]), fmaxf(sh[18], sh[19])),
                       fmaxf(fmaxf(sh[20], sh[21]), fmaxf(sh[22], sh[23])));
    amax = fmaxf(amax, 1e-5f);
    float scale = 127.0f / amax;

    __nv_bfloat162* qp = (__nv_bfloat162*)(g_xq + (size_t)t * D_MODEL);
    qp[2 * tid + 0]         = __floats2bfloat162_rn(QV(v0.x, scale), QV(v0.y, scale));
    qp[2 * tid + 1]         = __floats2bfloat162_rn(QV(v0.z, scale), QV(v0.w, scale));
    qp[2 * (tid + 256) + 0] = __floats2bfloat162_rn(QV(v1.x, scale), QV(v1.y, scale));
    qp[2 * (tid + 256) + 1] = __floats2bfloat162_rn(QV(v1.z, scale), QV(v1.w, scale));
    if (tid == 0) g_xinv[t] = amax * (1.0f / 127.0f);
}

// ---------------- GELU + LN + quant (h: d=8192) -> bf16, 256 threads ----------------
__global__ void ln_quant_h_kernel() {
    __shared__ float sh[24];
    const int t = blockIdx.x, tid = threadIdx.x;
    const int wid = tid >> 5, lane = tid & 31;
    const float4* rp = (const float4*)(g_h + (size_t)t * D_FF);
    float4 v[8];
    float s = 0.f;
#pragma unroll
    for (int j = 0; j < 8; j++) v[j] = rp[j * 256 + tid];
#pragma unroll
    for (int j = 0; j < 8; j++) {
        v[j].x = gelu_fast(v[j].x); v[j].y = gelu_fast(v[j].y);
        v[j].z = gelu_fast(v[j].z); v[j].w = gelu_fast(v[j].w);
        s += v[j].x + v[j].y + v[j].z + v[j].w;
    }
    for (int o = 16; o; o >>= 1) s += __shfl_xor_sync(0xffffffffu, s, o);
    if (lane == 0) sh[wid] = s;
    __syncthreads();
    float mu = (((sh[0] + sh[1]) + (sh[2] + sh[3])) + ((sh[4] + sh[5]) + (sh[6] + sh[7])))
               * (1.0f / D_FF);

    float vs = 0.f;
#pragma unroll
    for (int j = 0; j < 8; j++) {
        v[j].x -= mu; v[j].y -= mu; v[j].z -= mu; v[j].w -= mu;
        vs += v[j].x*v[j].x + v[j].y*v[j].y + v[j].z*v[j].z + v[j].w*v[j].w;
    }
    for (int o = 16; o; o >>= 1) vs += __shfl_xor_sync(0xffffffffu, vs, o);
    if (lane == 0) sh[8 + wid] = vs;
    __syncthreads();
    float var = (((sh[8] + sh[9]) + (sh[10] + sh[11])) + ((sh[12] + sh[13]) + (sh[14] + sh[15])))
                * (1.0f / D_FF);
    float rstd = rsqrtf(var + 1e-5f);

    float am = 0.f;
#pragma unroll
    for (int j = 0; j < 8; j++) {
        v[j].x *= rstd; v[j].y *= rstd; v[j].z *= rstd; v[j].w *= rstd;
        am = fmaxf(am, fmaxf(fmaxf(fabsf(v[j].x), fabsf(v[j].y)), fmaxf(fabsf(v[j].z), fabsf(v[j].w))));
    }
    for (int o = 16; o; o >>= 1) am = fmaxf(am, __shfl_xor_sync(0xffffffffu, am, o));
    if (lane == 0) sh[16 + wid] = am;
    __syncthreads();
    float amax = fmaxf(fmaxf(fmaxf(sh[16], sh[17]), fmaxf(sh[18], sh[19])),
                       fmaxf(fmaxf(sh[20], sh[21]), fmaxf(sh[22], sh[23])));
    amax = fmaxf(amax, 1e-5f);
    float scale = 127.0f / amax;

    __nv_bfloat162* qp = (__nv_bfloat162*)(g_hq + (size_t)t * D_FF);
#pragma unroll
    for (int j = 0; j < 8; j++) {
        qp[2 * (j * 256 + tid) + 0] = __floats2bfloat162_rn(QV(v[j].x, scale), QV(v[j].y, scale));
        qp[2 * (j * 256 + tid) + 1] = __floats2bfloat162_rn(QV(v[j].z, scale), QV(v[j].w, scale));
    }
    if (tid == 0) g_hinv[t] = amax * (1.0f / 127.0f);
}

// ---------------- launch: ln_x overlapped with weight chain; rest sequential ----------------
extern "C" void kernel_launch(void* const* d_in, const int* in_sizes, int n_in,
                              void* d_out, int out_size) {
    (void)in_sizes; (void)n_in; (void)out_size;
    const float* x  = (const float*)d_in[0];
    const float* w1 = (const float*)d_in[1];
    const float* b1 = (const float*)d_in[2];
    const float* w2 = (const float*)d_in[3];
    const float* b2 = (const float*)d_in[4];
    float* out = (float*)d_out;

    const size_t NW = (size_t)D_FF * D_MODEL;
    const int GEMM_SMEM = 3 * STAGE_BYTES;  // 96 KB

    cudaFuncSetAttribute(gemm_hmma<1>, cudaFuncAttributeMaxDynamicSharedMemorySize, GEMM_SMEM);
    cudaFuncSetAttribute(gemm_hmma<2>, cudaFuncAttributeMaxDynamicSharedMemorySize, GEMM_SMEM);

    static cudaStream_t sSide = [] {
        cudaStream_t s; cudaStreamCreateWithFlags(&s, cudaStreamNonBlocking); return s;
    }();
    static cudaEvent_t eFork = [] {
        cudaEvent_t e; cudaEventCreateWithFlags(&e, cudaEventDisableTiming); return e;
    }();
    static cudaEvent_t eX = [] {
        cudaEvent_t e; cudaEventCreateWithFlags(&e, cudaEventDisableTiming); return e;
    }();

    // resolve the stream the harness is capturing (or legacy default when eager)
    cudaStream_t M = cudaStreamLegacy;
    cudaStreamCaptureStatus cst = cudaStreamCaptureStatusNone;
    cudaStreamIsCapturing(cudaStreamPerThread, &cst);
    if (cst != cudaStreamCaptureStatusNone) M = cudaStreamPerThread;

    // fork: ln_quant_x runs concurrent with the weight chain (both input-only)
    cudaEventRecord(eFork, M);
    cudaStreamWaitEvent(sSide, eFork, 0);
    ln_quant_x_kernel<<<TOKENS, 256, 0, sSide>>>(x);
    cudaEventRecord(eX, sSide);

    absmean_stage1<<<dim3(1024, 2), 256, 0, M>>>(w1, w2, NW);
    quant_w_kernel<<<dim3(4096, 2), 256, 0, M>>>(w1, w2, NW);

    // join, then the proven sequential pipeline
    cudaStreamWaitEvent(M, eX, 0);
    gemm_hmma<1><<<dim3(D_FF / 128, TOKENS / 128), 128, GEMM_SMEM, M>>>(b1, nullptr);
    ln_quant_h_kernel<<<TOKENS, 256, 0, M>>>();
    gemm_hmma<2><<<dim3(D_MODEL / 128, TOKENS / 128), 128, GEMM_SMEM, M>>>(b2, out);
}

// round 17
// speedup vs baseline: 1.0140x; 1.0092x over previous
#include <cuda_runtime.h>
#include <cuda_bf16.h>
#include <math.h>
#include <stdint.h>

#define TOKENS  8192
#define D_MODEL 2048
#define D_FF    8192

// ---------------- scratch (static device globals) ----------------
__device__ double        g_part[2][1024];
__device__ float         g_wscale[2];
__device__ __nv_bfloat16 g_w1q[(size_t)D_FF * D_MODEL];
__device__ __nv_bfloat16 g_w2q[(size_t)D_MODEL * D_FF];
__device__ __nv_bfloat16 g_xq [(size_t)TOKENS * D_MODEL];
__device__ float         g_xinv[TOKENS];
__device__ float         g_h  [(size_t)TOKENS * D_FF];   // pre-GELU linear output
__device__ __nv_bfloat16 g_hq [(size_t)TOKENS * D_FF];
__device__ float         g_hinv[TOKENS];

// ---------------- PTX helpers ----------------
__device__ __forceinline__ uint32_t s2u(const void* p) {
    uint32_t a;
    asm("{ .reg .u64 t; cvta.to.shared.u64 t, %1; cvt.u32.u64 %0, t; }" : "=r"(a) : "l"(p));
    return a;
}
#define CP_ASYNC16(s, g) \
    asm volatile("cp.async.cg.shared.global [%0], [%1], 16;" :: "r"(s), "l"(g) : "memory")
#define CP_COMMIT()  asm volatile("cp.async.commit_group;" ::: "memory")
#define CP_WAIT(n)   asm volatile("cp.async.wait_group %0;" :: "n"(n) : "memory")

#define LDSM_X4(r, a) \
    asm volatile("ldmatrix.sync.aligned.m8n8.x4.shared.b16 {%0,%1,%2,%3}, [%4];" \
        : "=r"((r)[0]), "=r"((r)[1]), "=r"((r)[2]), "=r"((r)[3]) : "r"(a))

#define MMA_BF16(d, a, b0v, b1v) \
    asm volatile("mma.sync.aligned.m16n8k16.row.col.f32.bf16.bf16.f32 " \
        "{%0,%1,%2,%3}, {%4,%5,%6,%7}, {%8,%9}, {%0,%1,%2,%3};" \
        : "+f"((d)[0]), "+f"((d)[1]), "+f"((d)[2]), "+f"((d)[3]) \
        : "r"((a)[0]), "r"((a)[1]), "r"((a)[2]), "r"((a)[3]), "r"(b0v), "r"(b1v))

// ---------------- stage ROWS x 64 bf16 (128B/row), XOR-swizzled, 128 threads ----------------
template <int ROWS>
__device__ __forceinline__ void stage_tile(const __nv_bfloat16* g, int ld,
                                           uint32_t sbase, int tid) {
#pragma unroll
    for (int it = 0; it < ROWS / 16; ++it) {
        int idx = tid + it * 128;
        int row = idx >> 3, c = idx & 7;
        uint32_t saddr = sbase + row * 128 + ((c ^ (row & 7)) << 4);
        CP_ASYNC16(saddr, (const char*)(g + (size_t)row * ld) + c * 16);
    }
}

// ---------------- bf16 HMMA GEMM: out[M,N] = A[M,K] * B[N,K]^T (exact int) ----------------
// block 128x128, 4 warps (2x2), warp tile 64x64, 3-stage cp.async pipeline.
// Inner loop is fragment-pipelined: jp-major (1 ldsm feeds 8 mma), A frags
// double-buffered across ks, B frags double-buffered across jp, so mma never
// waits on ldsm except at the iteration head. Prefetches never cross the
// kt barrier (stage kt+1 is not guaranteed resident until next CP_WAIT).
#define STAGE_BYTES 32768
template <int MODE>
__global__ void __launch_bounds__(128, 2) gemm_hmma(const float* __restrict__ bias,
                                                    float* __restrict__ outp) {
    extern __shared__ __align__(128) char smem[];

    constexpr int K      = (MODE == 1) ? D_MODEL : D_FF;
    constexpr int KITERS = K / 64;
    constexpr int LDOUT  = (MODE == 1) ? D_FF : D_MODEL;

    const __nv_bfloat16* A = (MODE == 1) ? g_xq : g_hq;
    const __nv_bfloat16* B = (MODE == 1) ? g_w1q : g_w2q;
    const float* rowinv = (MODE == 1) ? g_xinv : g_hinv;
    float* out = (MODE == 1) ? g_h : outp;

    const int tid = threadIdx.x;
    const int wid = tid >> 5, lane = tid & 31;
    const int warpM = wid >> 1, warpN = wid & 1;
    const int m0 = blockIdx.y * 128, n0 = blockIdx.x * 128;

    const __nv_bfloat16* Abase = A + (size_t)m0 * K;
    const __nv_bfloat16* Bbase = B + (size_t)n0 * K;

    uint32_t sbase = s2u(smem);
    const int lr = lane & 7, gq = lane >> 3;

    const uint32_t aRow = (uint32_t)(warpM * 64 + lr + ((gq & 1) << 3));
    const uint32_t bRow = (uint32_t)(warpN * 64 + lr + ((gq >> 1) << 3));
    const int aCsel = gq >> 1;
    const int bCsel = gq & 1;

    float acc[4][8][4];
#pragma unroll
    for (int i = 0; i < 4; i++)
#pragma unroll
        for (int j = 0; j < 8; j++)
#pragma unroll
            for (int r = 0; r < 4; r++) acc[i][j][r] = 0.f;

    // prologue: stages 0 and 1
    stage_tile<128>(Abase, K, sbase, tid);
    stage_tile<128>(Bbase, K, sbase + 16384, tid);
    CP_COMMIT();
    stage_tile<128>(Abase + 64, K, sbase + STAGE_BYTES, tid);
    stage_tile<128>(Bbase + 64, K, sbase + STAGE_BYTES + 16384, tid);
    CP_COMMIT();

    for (int kt = 0; kt < KITERS; ++kt) {
        CP_WAIT(1);
        __syncthreads();   // stage-kt visible to all; prior-iter reads complete

        const bool doStage = (kt + 2 < KITERS);
        const uint32_t sn = sbase + ((kt + 2) % 3) * STAGE_BYTES;
        const __nv_bfloat16* An = Abase + (kt + 2) * 64;
        const __nv_bfloat16* Bn = Bbase + (kt + 2) * 64;

        const uint32_t sA = sbase + (kt % 3) * STAGE_BYTES;
        const uint32_t aLane = sA + aRow * 128;
        const uint32_t bLane = sA + 16384 + bRow * 128;

        uint32_t ar[2][4][4], br[2][4];

        // head loads for ks=0 (the only exposed ldsm latency per kt)
        {
            const uint32_t ca0 = (uint32_t)((aCsel ^ lr) << 4);
            const uint32_t cb0 = (uint32_t)((bCsel ^ lr) << 4);
#pragma unroll
            for (int i = 0; i < 4; i++) LDSM_X4(ar[0][i], aLane + i * 2048 + ca0);
            LDSM_X4(br[0], bLane + cb0);
        }
#pragma unroll
        for (int ks = 0; ks < 4; ++ks) {
            const int ab = ks & 1;
            // staging cp.async quarter (unchanged placement)
            if (doStage) {
#pragma unroll
                for (int it = 2 * ks; it < 2 * ks + 2; ++it) {
                    int idx = tid + it * 128;
                    int row = idx >> 3, c = idx & 7;
                    uint32_t off = (uint32_t)(row * 128 + ((c ^ (row & 7)) << 4));
                    CP_ASYNC16(sn + off, (const char*)(An + (size_t)row * K) + c * 16);
                    CP_ASYNC16(sn + 16384 + off, (const char*)(Bn + (size_t)row * K) + c * 16);
                }
            }
            // prefetch next-ks A frags into the other buffer
            if (ks < 3) {
                const uint32_t can = (uint32_t)((((ks + 1) * 2 + aCsel) ^ lr) << 4);
#pragma unroll
                for (int i = 0; i < 4; i++) LDSM_X4(ar[ab ^ 1][i], aLane + i * 2048 + can);
            }
            const uint32_t cb = (uint32_t)(((ks * 2 + bCsel) ^ lr) << 4);
#pragma unroll
            for (int jp = 0; jp < 4; ++jp) {
                const int bb = jp & 1;
                // prefetch next B frag (next jp, or next ks's jp=0)
                if (jp < 3) {
                    LDSM_X4(br[bb ^ 1], bLane + (jp + 1) * 2048 + cb);
                } else if (ks < 3) {
                    const uint32_t cbn = (uint32_t)((((ks + 1) * 2 + bCsel) ^ lr) << 4);
                    LDSM_X4(br[bb ^ 1], bLane + cbn);
                }
#pragma unroll
                for (int i = 0; i < 4; i++) {
                    MMA_BF16(acc[i][2 * jp],     ar[ab][i], br[bb][0], br[bb][1]);
                    MMA_BF16(acc[i][2 * jp + 1], ar[ab][i], br[bb][2], br[bb][3]);
                }
            }
        }
        CP_COMMIT();       // exactly one group per iter
    }

    // ---------------- epilogue: scale + bias, float2 stores (no GELU here) ----------------
    const float ws = g_wscale[MODE - 1];
    const int rbase = m0 + warpM * 64 + (lane >> 2);
    const int cbase = n0 + warpN * 64 + (lane & 3) * 2;
#pragma unroll
    for (int i = 0; i < 4; i++) {
        const int r0 = rbase + i * 16;
        const float sc0 = rowinv[r0] * ws;
        const float sc1 = rowinv[r0 + 8] * ws;
#pragma unroll
        for (int j = 0; j < 8; j++) {
            const int c = cbase + j * 8;
            const float bx = bias[c], by = bias[c + 1];
            float2 v0, v1;
            v0.x = acc[i][j][0] * sc0 + bx;
            v0.y = acc[i][j][1] * sc0 + by;
            v1.x = acc[i][j][2] * sc1 + bx;
            v1.y = acc[i][j][3] * sc1 + by;
            *(float2*)(out + (size_t)r0 * LDOUT + c) = v0;
            *(float2*)(out + (size_t)(r0 + 8) * LDOUT + c) = v1;
        }
    }
}

// ---------------- weight absmean partials (single weight) ----------------
__global__ void absmean_stage1(const float* __restrict__ w, size_t n, int idx) {
    __shared__ double sh[256];
    double s = 0.0;
    for (size_t i = (size_t)blockIdx.x * 256 + threadIdx.x; i < n; i += (size_t)256 * 1024)
        s += fabsf(w[i]);
    sh[threadIdx.x] = s; __syncthreads();
    for (int st = 128; st > 0; st >>= 1) {
        if (threadIdx.x < st) sh[threadIdx.x] += sh[threadIdx.x + st];
        __syncthreads();
    }
    if (threadIdx.x == 0) g_part[idx][blockIdx.x] = sh[0];
}

// ---------------- ternary weight quant -> bf16, fused (redundant) scale fold ----------------
__global__ void quant_w_kernel(const float* __restrict__ w, size_t n, int idx) {
    __shared__ double sh[256];
    const int tid = threadIdx.x;
    double s = g_part[idx][tid] + g_part[idx][tid + 256] +
               g_part[idx][tid + 512] + g_part[idx][tid + 768];
    sh[tid] = s; __syncthreads();
    for (int st = 128; st > 0; st >>= 1) {
        if (tid < st) sh[tid] += sh[tid + st];
        __syncthreads();
    }
    const float sc = (float)fmax(sh[0] / (double)n, 1e-8);
    if (blockIdx.x == 0 && tid == 0) g_wscale[idx] = sc;

    __nv_bfloat16* q = idx ? g_w2q : g_w1q;
    for (size_t i = (size_t)blockIdx.x * blockDim.x + tid; i < n;
         i += (size_t)4096 * blockDim.x) {
        float v = rintf(w[i] / sc);
        v = fmaxf(-1.0f, fminf(1.0f, v));
        q[i] = __float2bfloat16(v);
    }
}

#define QV(a, scale) fminf(127.f, fmaxf(-128.f, rintf((a) * (scale))))

// fast erf (Abramowitz-Stegun 7.1.26, |abs err| ~1.5e-7) -> exact-enough GELU
__device__ __forceinline__ float gelu_fast(float x) {
    float z = x * 0.7071067811865476f;
    float az = fabsf(z);
    float t = __fdividef(1.0f, 1.0f + 0.3275911f * az);
    float p = ((((1.061405429f * t - 1.453152027f) * t + 1.421413741f) * t
               - 0.284496736f) * t + 0.254829592f) * t;
    float er = 1.0f - p * __expf(-az * az);
    er = copysignf(er, z);
    return 0.5f * x * (1.0f + er);
}

// ---------------- fused LN + per-token absmax int8 fake-quant -> bf16 (x: d=2048) ----------------
__global__ void ln_quant_x_kernel(const float* __restrict__ x) {
    __shared__ float sh[24];
    const int t = blockIdx.x, tid = threadIdx.x;
    const int wid = tid >> 5, lane = tid & 31;
    const float4* rp = (const float4*)(x + (size_t)t * D_MODEL);
    float4 v0 = rp[tid], v1 = rp[tid + 256];

    float s = v0.x + v0.y + v0.z + v0.w + v1.x + v1.y + v1.z + v1.w;
    for (int o = 16; o; o >>= 1) s += __shfl_xor_sync(0xffffffffu, s, o);
    if (lane == 0) sh[wid] = s;
    __syncthreads();
    float mu = (((sh[0] + sh[1]) + (sh[2] + sh[3])) + ((sh[4] + sh[5]) + (sh[6] + sh[7])))
               * (1.0f / D_MODEL);

    v0.x -= mu; v0.y -= mu; v0.z -= mu; v0.w -= mu;
    v1.x -= mu; v1.y -= mu; v1.z -= mu; v1.w -= mu;
    float vs = v0.x*v0.x + v0.y*v0.y + v0.z*v0.z + v0.w*v0.w
             + v1.x*v1.x + v1.y*v1.y + v1.z*v1.z + v1.w*v1.w;
    for (int o = 16; o; o >>= 1) vs += __shfl_xor_sync(0xffffffffu, vs, o);
    if (lane == 0) sh[8 + wid] = vs;
    __syncthreads();
    float var = (((sh[8] + sh[9]) + (sh[10] + sh[11])) + ((sh[12] + sh[13]) + (sh[14] + sh[15])))
                * (1.0f / D_MODEL);
    float rstd = rsqrtf(var + 1e-5f);

    v0.x *= rstd; v0.y *= rstd; v0.z *= rstd; v0.w *= rstd;
    v1.x *= rstd; v1.y *= rstd; v1.z *= rstd; v1.w *= rstd;
    float am = fmaxf(fmaxf(fmaxf(fabsf(v0.x), fabsf(v0.y)), fmaxf(fabsf(v0.z), fabsf(v0.w))),
                     fmaxf(fmaxf(fabsf(v1.x), fabsf(v1.y)), fmaxf(fabsf(v1.z), fabsf(v1.w))));
    for (int o = 16; o; o >>= 1) am = fmaxf(am, __shfl_xor_sync(0xffffffffu, am, o));
    if (lane == 0) sh[16 + wid] = am;
    __syncthreads();
    float amax = fmaxf(fmaxf(fmaxf(sh[16], sh[17]), fmaxf(sh[18], sh[19])),
                       fmaxf(fmaxf(sh[20], sh[21]), fmaxf(sh[22], sh[23])));
    amax = fmaxf(amax, 1e-5f);
    float scale = 127.0f / amax;

    __nv_bfloat162* qp = (__nv_bfloat162*)(g_xq + (size_t)t * D_MODEL);
    qp[2 * tid + 0]         = __floats2bfloat162_rn(QV(v0.x, scale), QV(v0.y, scale));
    qp[2 * tid + 1]         = __floats2bfloat162_rn(QV(v0.z, scale), QV(v0.w, scale));
    qp[2 * (tid + 256) + 0] = __floats2bfloat162_rn(QV(v1.x, scale), QV(v1.y, scale));
    qp[2 * (tid + 256) + 1] = __floats2bfloat162_rn(QV(v1.z, scale), QV(v1.w, scale));
    if (tid == 0) g_xinv[t] = amax * (1.0f / 127.0f);
}

// ---------------- GELU + LN + quant (h: d=8192) -> bf16, 256 threads ----------------
__global__ void ln_quant_h_kernel() {
    __shared__ float sh[24];
    const int t = blockIdx.x, tid = threadIdx.x;
    const int wid = tid >> 5, lane = tid & 31;
    const float4* rp = (const float4*)(g_h + (size_t)t * D_FF);
    float4 v[8];
    float s = 0.f;
#pragma unroll
    for (int j = 0; j < 8; j++) v[j] = rp[j * 256 + tid];
#pragma unroll
    for (int j = 0; j < 8; j++) {
        v[j].x = gelu_fast(v[j].x); v[j].y = gelu_fast(v[j].y);
        v[j].z = gelu_fast(v[j].z); v[j].w = gelu_fast(v[j].w);
        s += v[j].x + v[j].y + v[j].z + v[j].w;
    }
    for (int o = 16; o; o >>= 1) s += __shfl_xor_sync(0xffffffffu, s, o);
    if (lane == 0) sh[wid] = s;
    __syncthreads();
    float mu = (((sh[0] + sh[1]) + (sh[2] + sh[3])) + ((sh[4] + sh[5]) + (sh[6] + sh[7])))
               * (1.0f / D_FF);

    float vs = 0.f;
#pragma unroll
    for (int j = 0; j < 8; j++) {
        v[j].x -= mu; v[j].y -= mu; v[j].z -= mu; v[j].w -= mu;
        vs += v[j].x*v[j].x + v[j].y*v[j].y + v[j].z*v[j].z + v[j].w*v[j].w;
    }
    for (int o = 16; o; o >>= 1) vs += __shfl_xor_sync(0xffffffffu, vs, o);
    if (lane == 0) sh[8 + wid] = vs;
    __syncthreads();
    float var = (((sh[8] + sh[9]) + (sh[10] + sh[11])) + ((sh[12] + sh[13]) + (sh[14] + sh[15])))
                * (1.0f / D_FF);
    float rstd = rsqrtf(var + 1e-5f);

    float am = 0.f;
#pragma unroll
    for (int j = 0; j < 8; j++) {
        v[j].x *= rstd; v[j].y *= rstd; v[j].z *= rstd; v[j].w *= rstd;
        am = fmaxf(am, fmaxf(fmaxf(fabsf(v[j].x), fabsf(v[j].y)), fmaxf(fabsf(v[j].z), fabsf(v[j].w))));
    }
    for (int o = 16; o; o >>= 1) am = fmaxf(am, __shfl_xor_sync(0xffffffffu, am, o));
    if (lane == 0) sh[16 + wid] = am;
    __syncthreads();
    float amax = fmaxf(fmaxf(fmaxf(sh[16], sh[17]), fmaxf(sh[18], sh[19])),
                       fmaxf(fmaxf(sh[20], sh[21]), fmaxf(sh[22], sh[23])));
    amax = fmaxf(amax, 1e-5f);
    float scale = 127.0f / amax;

    __nv_bfloat162* qp = (__nv_bfloat162*)(g_hq + (size_t)t * D_FF);
#pragma unroll
    for (int j = 0; j < 8; j++) {
        qp[2 * (j * 256 + tid) + 0] = __floats2bfloat162_rn(QV(v[j].x, scale), QV(v[j].y, scale));
        qp[2 * (j * 256 + tid) + 1] = __floats2bfloat162_rn(QV(v[j].z, scale), QV(v[j].w, scale));
    }
    if (tid == 0) g_hinv[t] = amax * (1.0f / 127.0f);
}

// ---------------- launch: ln_x + w2-chain overlapped; gemm1 at ncu index 3 ----------------
extern "C" void kernel_launch(void* const* d_in, const int* in_sizes, int n_in,
                              void* d_out, int out_size) {
    (void)in_sizes; (void)n_in; (void)out_size;
    const float* x  = (const float*)d_in[0];
    const float* w1 = (const float*)d_in[1];
    const float* b1 = (const float*)d_in[2];
    const float* w2 = (const float*)d_in[3];
    const float* b2 = (const float*)d_in[4];
    float* out = (float*)d_out;

    const size_t NW = (size_t)D_FF * D_MODEL;
    const int GEMM_SMEM = 3 * STAGE_BYTES;  // 96 KB

    cudaFuncSetAttribute(gemm_hmma<1>, cudaFuncAttributeMaxDynamicSharedMemorySize, GEMM_SMEM);
    cudaFuncSetAttribute(gemm_hmma<2>, cudaFuncAttributeMaxDynamicSharedMemorySize, GEMM_SMEM);

    static cudaStream_t sSide = [] {
        cudaStream_t s; cudaStreamCreateWithFlags(&s, cudaStreamNonBlocking); return s;
    }();
    static cudaStream_t sW2 = [] {
        cudaStream_t s; cudaStreamCreateWithFlags(&s, cudaStreamNonBlocking); return s;
    }();
    static cudaEvent_t eFork = [] {
        cudaEvent_t e; cudaEventCreateWithFlags(&e, cudaEventDisableTiming); return e;
    }();
    static cudaEvent_t eX = [] {
        cudaEvent_t e; cudaEventCreateWithFlags(&e, cudaEventDisableTiming); return e;
    }();
    static cudaEvent_t eW1 = [] {
        cudaEvent_t e; cudaEventCreateWithFlags(&e, cudaEventDisableTiming); return e;
    }();
    static cudaEvent_t eW2 = [] {
        cudaEvent_t e; cudaEventCreateWithFlags(&e, cudaEventDisableTiming); return e;
    }();

    // resolve the stream the harness is capturing (or legacy default when eager)
    cudaStream_t M = cudaStreamLegacy;
    cudaStreamCaptureStatus cst = cudaStreamCaptureStatusNone;
    cudaStreamIsCapturing(cudaStreamPerThread, &cst);
    if (cst != cudaStreamCaptureStatusNone) M = cudaStreamPerThread;

    // fork: ln_quant_x concurrent with w1 chain
    cudaEventRecord(eFork, M);
    cudaStreamWaitEvent(sSide, eFork, 0);
    ln_quant_x_kernel<<<TOKENS, 256, 0, sSide>>>(x);                             // launch 0
    cudaEventRecord(eX, sSide);

    absmean_stage1<<<1024, 256, 0, M>>>(w1, NW, 0);                              // launch 1
    quant_w_kernel<<<4096, 256, 0, M>>>(w1, NW, 0);                              // launch 2
    cudaEventRecord(eW1, M);

    cudaStreamWaitEvent(M, eX, 0);
    gemm_hmma<1><<<dim3(D_FF / 128, TOKENS / 128), 128, GEMM_SMEM, M>>>(b1, nullptr); // launch 3 <- ncu
    ln_quant_h_kernel<<<TOKENS, 256, 0, M>>>();                                  // launch 4

    // w2 chain on its own stream: starts after w1 chain, executes in gemm1's drain
    cudaStreamWaitEvent(sW2, eW1, 0);
    absmean_stage1<<<1024, 256, 0, sW2>>>(w2, NW, 1);                            // launch 5
    quant_w_kernel<<<4096, 256, 0, sW2>>>(w2, NW, 1);                            // launch 6
    cudaEventRecord(eW2, sW2);

    cudaStreamWaitEvent(M, eW2, 0);
    gemm_hmma<2><<<dim3(D_MODEL / 128, TOKENS / 128), 128, GEMM_SMEM, M>>>(b2, out); // launch 7
}